// round 13
// baseline (speedup 1.0000x reference)
#include <cuda_runtime.h>
#include <cuda_bf16.h>
#include <cstdint>

// Resample2d bilinear warp — smem-staged gather, 16B cp.async depth-3
// pipeline, LARGE tile to amortize halo.
// input1: [8,64,384,512] f32, input2(flow): [8,2,384,512] f32, out NCHW f32.
//
// R12 (BH8xBW32, 241us): staging worked but halo amplification was 2.58x
// (15 staged rows per 8 output rows); per-px L1 cost 0.51 cyc vs direct's
// 0.60 minus barrier overhead = net loss vs R2 (213us). This round: BH=16 x
// BW=64, TPB=1024 -> staged 23x76 = 1.71x amplification, per-px L1 ~0.40
// cyc. Same proven pipeline: cp.async.cg 16B, 4 buffers, depth-3 groups,
// one __syncthreads per channel. Margin-3 tile, border-clamped rows; staged
// values bit-equal to global, out-of-tile lanes (~0.3%) use the identical
// global-LDG path.

#define B_ 8
#define D_ 64
#define H_ 384
#define W_ 512
#define PLANE_ (H_ * W_)
#define TPB 1024
#define BH 16
#define BW 64
#define MGY 3                 // row margin
#define NR (BH + 2 * MGY + 1) // 23 staged rows
#define NC 76                 // staged cols (span 73, padded to mult of 4)
#define NC16 (NC / 4)         // 19 16B ops per row
#define SSTR NC               // smem row stride (16B aligned)
#define TSZ (NR * SSTR)       // 1748 floats
#define NOPS (NR * NC16)      // 437 16B copies per channel

__device__ __forceinline__ unsigned smem_u32(const void* p) {
    unsigned a;
    asm("{ .reg .u64 t; cvta.to.shared.u64 t, %1; cvt.u32.u64 %0, t; }"
        : "=r"(a) : "l"(p));
    return a;
}
#define CP16(dst_u32, src_ptr) \
    asm volatile("cp.async.cg.shared.global [%0], [%1], 16;" \
                 :: "r"(dst_u32), "l"(src_ptr))
#define CP_COMMIT() asm volatile("cp.async.commit_group;" ::: "memory")
#define CP_WAIT2()  asm volatile("cp.async.wait_group 2;" ::: "memory")

__global__ __launch_bounds__(TPB)
void resample2d_kernel(const float* __restrict__ img,
                       const float* __restrict__ flow,
                       float* __restrict__ out)
{
    __shared__ float tile[4][TSZ];

    const int tid = threadIdx.x;
    int gx = blockIdx.x;
    const int wb = gx & 7;               // W/BW = 8
    gx >>= 3;
    const int hb = gx % (H_ / BH);       // 24
    const int b  = gx / (H_ / BH);
    const int h0 = hb * BH;
    const int w0 = wb * BW;
    const int h = h0 + (tid >> 6);       // tid/64 -> row 0..15
    const int w = w0 + (tid & 63);

    // ---- flow / weights / indices ----
    const unsigned foff = (unsigned)b * (2u * PLANE_) + (unsigned)h * W_ + w;
    const float u = __ldg(flow + foff);
    const float v = __ldg(flow + foff + PLANE_);

    float fx = (float)w + u;
    float fy = (float)h + v;
    fx = fminf(fmaxf(fx, 0.0f), (float)(W_ - 1));
    fy = fminf(fmaxf(fy, 0.0f), (float)(H_ - 1));
    const int x0 = min((int)fx, W_ - 2);
    const int y0 = min((int)fy, H_ - 2);
    const float wx = fx - (float)x0;
    const float wy = fy - (float)y0;

    const float w00 = (1.0f - wy) * (1.0f - wx);
    const float w01 = (1.0f - wy) * wx;
    const float w10 = wy * (1.0f - wx);
    const float w11 = wy * wx;

    // ---- tile geometry ----
    const int ylo = h0 - MGY;                        // content rows clamped
    int xlo = w0 - 4;
    xlo = max(0, min(xlo, W_ - NC));                 // multiple of 4 always

    const int tr = y0 - ylo;
    const int tc = x0 - xlo;
    const bool ok = (tr >= 0) & (tr <= NR - 2) & (tc >= 0) & (tc <= NC - 2);
    const int sb = tr * SSTR + tc;

    // ---- one 16B staging slot per thread (tid < NOPS = 437) ----
    const float* pbase = img + (size_t)b * (D_ * PLANE_);
    const bool cpy = (tid < NOPS);
    unsigned gso = 0, sso = 0;
    if (cpy) {
        const int r = tid / NC16;
        const int c16 = tid - r * NC16;
        const int gy = min(max(ylo + r, 0), H_ - 1);
        gso = (unsigned)(gy * W_ + xlo + c16 * 4);
        sso = (unsigned)(r * SSTR + c16 * 4) * 4u;
    }
    const unsigned smb = smem_u32(&tile[0][0]);

    const float* gp = pbase + (unsigned)y0 * W_ + (unsigned)x0;   // fallback
    float* po = out + (size_t)b * (D_ * PLANE_) + (unsigned)h * W_ + (unsigned)w;

    // ---- prologue: channels 0..2 into buffers 0..2 ----
    #pragma unroll
    for (int d = 0; d < 3; ++d) {
        if (cpy) {
            CP16(smb + (unsigned)(d * TSZ) * 4u + sso,
                 pbase + (size_t)d * PLANE_ + gso);
        }
        CP_COMMIT();
    }

    // ---- main loop: one barrier per channel ----
    for (int d = 0; d < D_; ++d) {
        CP_WAIT2();              // group for channel d complete
        __syncthreads();         // publish smem; frees buffer (d-1)&3

        if (d + 3 < D_ && cpy) { // refill the just-freed buffer
            const int dn = d + 3;
            CP16(smb + (unsigned)((dn & 3) * TSZ) * 4u + sso,
                 pbase + (size_t)dn * PLANE_ + gso);
        }
        CP_COMMIT();

        float a00, a01, a10, a11;
        if (ok) {
            const float* tb = &tile[d & 3][0];
            a00 = tb[sb];
            a01 = tb[sb + 1];
            a10 = tb[sb + SSTR];
            a11 = tb[sb + SSTR + 1];
        } else {
            const float* g = gp + (size_t)d * PLANE_;
            a00 = __ldg(g);
            a01 = __ldg(g + 1);
            a10 = __ldg(g + W_);
            a11 = __ldg(g + W_ + 1);
        }
        float r = w00 * a00;
        r = fmaf(w01, a01, r);
        r = fmaf(w10, a10, r);
        r = fmaf(w11, a11, r);
        po[(size_t)d * PLANE_] = r;
    }
}

extern "C" void kernel_launch(void* const* d_in, const int* in_sizes, int n_in,
                              void* d_out, int out_size)
{
    const float* img  = (const float*)d_in[0];
    const float* flow = (const float*)d_in[1];
    float* out = (float*)d_out;

    dim3 grid((W_ / BW) * (H_ / BH) * B_);   // 8 * 24 * 8 = 1536
    dim3 block(TPB);
    resample2d_kernel<<<grid, block>>>(img, flow, out);
}

// round 14
// speedup vs baseline: 1.2333x; 1.2333x over previous
#include <cuda_runtime.h>
#include <cuda_bf16.h>

// Resample2d bilinear warp — direct scalar gather (proven optimal shape),
// channel-split grid for tail smoothing + streaming stores.
// input1: [8,64,384,512] f32, input2(flow): [8,2,384,512] f32, out NCHW f32.
//
// Conclusion from R2-R13: the divergent-gather l1tex wavefront cost is the
// floor (~0.6 wf/px); staging (smem/cp.async/vector/TMU) always pays >= that.
// R2's direct kernel sits at the floor but at 84% L1 utilization. Residual
// lever: cross-SM load imbalance (B300 spread model) -> split the 64-channel
// loop across 4 blocks (16 ch each, ~4us blocks, 24576 total) so slow blocks
// (bad gather locality) don't leave SMs idle at wave tails. Flow is re-read
// 4x (+0.15% traffic). Streaming stores keep write-once output from
// displacing gather-reused lines in L2.

#define B_ 8
#define D_ 64
#define H_ 384
#define W_ 512
#define PLANE_ (H_ * W_)
#define TPB 256
#define DCH 16                 // channels per block
#define DSPLIT (D_ / DCH)      // 4

__global__ __launch_bounds__(TPB)
void resample2d_kernel(const float* __restrict__ img,
                       const float* __restrict__ flow,
                       float* __restrict__ out)
{
    // blockIdx.x = ((b*H + h)*WCHUNKS + wc)*DSPLIT + ds
    int bid = blockIdx.x;
    const int ds = bid & (DSPLIT - 1);
    bid >>= 2;
    const int wc = bid & 1;                  // W/TPB = 2
    bid >>= 1;
    const int h = bid % H_;
    const int b = bid / H_;
    const int w = wc * TPB + threadIdx.x;
    const int d0 = ds * DCH;

    // flow [B,2,H,W]
    const unsigned foff = (unsigned)b * (2u * PLANE_) + (unsigned)h * W_ + w;
    const float u = __ldg(flow + foff);
    const float v = __ldg(flow + foff + PLANE_);

    float fx = (float)w + u;
    float fy = (float)h + v;
    fx = fminf(fmaxf(fx, 0.0f), (float)(W_ - 1));
    fy = fminf(fmaxf(fy, 0.0f), (float)(H_ - 1));
    const int x0 = min((int)fx, W_ - 2);
    const int y0 = min((int)fy, H_ - 2);
    const float wx = fx - (float)x0;
    const float wy = fy - (float)y0;

    const float w00 = (1.0f - wy) * (1.0f - wx);
    const float w01 = (1.0f - wy) * wx;
    const float w10 = wy * (1.0f - wx);
    const float w11 = wy * wx;

    // 32-bit element offsets (tensor = 100.6M elems < 2^31)
    unsigned o0 = (unsigned)b * (D_ * PLANE_) + (unsigned)(d0) * PLANE_
                + (unsigned)y0 * W_ + (unsigned)x0;
    unsigned o1 = o0 + W_;
    unsigned oo = (unsigned)b * (D_ * PLANE_) + (unsigned)(d0) * PLANE_
                + (unsigned)h * W_ + (unsigned)w;

    #pragma unroll
    for (int d = 0; d < DCH; ++d) {
        const float a00 = __ldg(img + o0);
        const float a01 = __ldg(img + o0 + 1);
        const float a10 = __ldg(img + o1);
        const float a11 = __ldg(img + o1 + 1);
        float r = w00 * a00;
        r = fmaf(w01, a01, r);
        r = fmaf(w10, a10, r);
        r = fmaf(w11, a11, r);
        __stcs(out + oo, r);
        o0 += PLANE_;
        o1 += PLANE_;
        oo += PLANE_;
    }
}

extern "C" void kernel_launch(void* const* d_in, const int* in_sizes, int n_in,
                              void* d_out, int out_size)
{
    const float* img  = (const float*)d_in[0];
    const float* flow = (const float*)d_in[1];
    float* out = (float*)d_out;

    dim3 grid(B_ * H_ * (W_ / TPB) * DSPLIT);   // 8*384*2*4 = 24576
    dim3 block(TPB);
    resample2d_kernel<<<grid, block>>>(img, flow, out);
}